// round 8
// baseline (speedup 1.0000x reference)
#include <cuda_runtime.h>
#include <cuda_fp16.h>
#include <cstdint>
#include <math.h>

#define BB 32
#define SS 64
#define CC 256
#define N2 4096

__device__ int      g_videoOf[SS];
__device__ int      g_topk[SS];
__device__ float    g_negsum[SS];
__device__ float    g_all[SS * SS];
__device__ uint4    g_Aimg[2048];        // 32KB fp16 A, ldmatrix-swizzled
__device__ uint4    g_Bimg4[4194304];    // 64MB fp16 B image, k-major, 16B-aligned
__device__ float    g_sinv[32 * 32 * 128];
__device__ unsigned g_done;

__device__ __forceinline__ uint32_t smem_u32(const void* p) {
    uint32_t a;
    asm("{ .reg .u64 t; cvta.to.shared.u64 t, %1; cvt.u32.u64 %0, t; }" : "=r"(a) : "l"(p));
    return a;
}
#define CP16(dst, src) \
    asm volatile("cp.async.cg.shared.global [%0], [%1], 16;" :: "r"(dst), "l"(src))
#define CP_COMMIT() asm volatile("cp.async.commit_group;")
#define LDSM4(r0, r1, r2, r3, addr) \
    asm volatile("ldmatrix.sync.aligned.m8n8.x4.shared.b16 {%0,%1,%2,%3}, [%4];" \
                 : "=r"(r0), "=r"(r1), "=r"(r2), "=r"(r3) : "r"(addr))
#define MMAF16(d, a0, a1, a2, a3, b0, b1) \
    asm volatile("mma.sync.aligned.m16n8k16.row.col.f32.f16.f16.f32 " \
                 "{%0,%1,%2,%3}, {%4,%5,%6,%7}, {%8,%9}, {%0,%1,%2,%3};" \
                 : "+f"((d)[0]), "+f"((d)[1]), "+f"((d)[2]), "+f"((d)[3]) \
                 : "r"(a0), "r"(a1), "r"(a2), "r"(a3), "r"(b0), "r"(b1))

// ===========================================================================
// k_convert: bid<1024 = (b,t) tile: fp32 triangle -> fp16 B image + sinv.
//            bid>=1024 = prep (sentence normalize/A image, argmax, init).
#define CV_SMEM (4 * 16384 + 1024)
__global__ void __launch_bounds__(256) k_convert(const float* __restrict__ video,
                                                 const float* __restrict__ sents,
                                                 const float* __restrict__ iou,
                                                 const int* __restrict__ ntgt) {
    int bid = blockIdx.x, tid = threadIdx.x;
    if (bid >= 1024) {
        int pb = bid - 1024;
        if (pb == 64) {
            if (tid < SS) g_negsum[tid] = 0.f;
            if (tid == 0) {
                g_done = 0u;
                int s = 0;
                for (int b = 0; b < BB; b++) {
                    int n = ntgt[b];
                    for (int k = 0; k < n && s < SS; k++) g_videoOf[s++] = b;
                }
                for (; s < SS; s++) g_videoOf[s] = BB - 1;
            }
            return;
        }
        int s = pb;
        int lane = tid & 31, w = tid >> 5;
        __shared__ float wsum[8];
        __shared__ float amax[8];
        __shared__ int   aidx[8];
        float x = sents[s * CC + tid];
        float q = x * x;
#pragma unroll
        for (int o = 16; o; o >>= 1) q += __shfl_xor_sync(~0u, q, o);
        if (lane == 0) wsum[w] = q;
        __syncthreads();
        float tot = wsum[0] + wsum[1] + wsum[2] + wsum[3] +
                    wsum[4] + wsum[5] + wsum[6] + wsum[7];
        float inv = 1.f / fmaxf(sqrtf(tot), 1e-12f);
        __half h = __float2half_rn(x * inv);
        int c = tid;
        int off = s * 512 + (((c >> 3) ^ (s & 7)) << 4) + (c & 7) * 2;
        *(__half*)((char*)g_Aimg + off) = h;

        float best = -1.f;
        int bi = 0;
        const float* irow = iou + (size_t)s * N2;
#pragma unroll
        for (int k = 0; k < 16; k++) {
            int ij = tid + 256 * k;
            if ((ij & 63) >= (ij >> 6)) {
                float v = irow[ij];
                if (v > best) { best = v; bi = ij; }
            }
        }
#pragma unroll
        for (int o = 16; o; o >>= 1) {
            float ov = __shfl_xor_sync(~0u, best, o);
            int   oi = __shfl_xor_sync(~0u, bi, o);
            if (ov > best || (ov == best && oi < bi)) { best = ov; bi = oi; }
        }
        if (lane == 0) { amax[w] = best; aidx[w] = bi; }
        __syncthreads();
        if (tid == 0) {
            float bb = amax[0]; int ii = aidx[0];
            for (int k = 1; k < 8; k++)
                if (amax[k] > bb || (amax[k] == bb && aidx[k] < ii)) { bb = amax[k]; ii = aidx[k]; }
            g_topk[s] = ii;
        }
        return;
    }

    // ---- convert tile ----
    extern __shared__ __align__(128) char sm[];
    uint32_t sb = smem_u32(sm);
    int t = bid & 31, b = bid >> 5;
    int ij0 = t * 128, i0 = 2 * t;
    int f0 = i0 >> 3, f1 = (i0 + 1) >> 3;
    int pstart0 = f0 * 8, pstart1 = 64 + f1 * 8;
    int seg0u = 16 - 2 * f0;
    int upr = 32 - 2 * (f0 + f1);
    float* ssq = (float*)(sm + 65536);

    int lch = tid >> 3, lj = tid & 7;
    const float* gch = video + (size_t)b * CC * N2 + ij0 + (size_t)lch * N2;
    uint32_t srow_dst = sb + lch * 512;

#pragma unroll
    for (int cc = 0; cc < 2; cc++) {
#pragma unroll
        for (int u4 = 0; u4 < 4; u4++) {
            int u = lj + u4 * 8;
            if (u < upr) {
                int prop = (u < seg0u) ? (pstart0 + 4 * u) : (pstart1 + 4 * (u - seg0u));
                CP16(srow_dst + cc * 16384 + prop * 4, gch + (size_t)cc * 32 * N2 + prop);
            }
        }
        CP_COMMIT();
    }

    int p = tid & 127, half = tid >> 7;
    bool active = (p < 64) ? (p >= pstart0) : (p >= pstart1);
    __half* orow = (__half*)g_Bimg4 + ((size_t)((b * 32 + t) * 128) + p) * 256;
    float myssq = 0.f;

    for (int ch = 0; ch < 8; ch++) {
        if (ch + 2 < 8) {
            uint32_t sd = srow_dst + ((ch + 2) & 3) * 16384;
            const float* gs = gch + (size_t)(ch + 2) * 32 * N2;
#pragma unroll
            for (int u4 = 0; u4 < 4; u4++) {
                int u = lj + u4 * 8;
                if (u < upr) {
                    int prop = (u < seg0u) ? (pstart0 + 4 * u) : (pstart1 + 4 * (u - seg0u));
                    CP16(sd + prop * 4, gs + prop);
                }
            }
        }
        CP_COMMIT();
        asm volatile("cp.async.wait_group 2;");
        __syncthreads();
        if (active) {
            const char* srow = sm + (ch & 3) * 16384 + p * 4;
            uint32_t wv[8];
#pragma unroll
            for (int k = 0; k < 16; k += 2) {
                int cl = half * 16 + k;
                float x0 = *(const float*)(srow + (size_t)cl * 512);
                float x1 = *(const float*)(srow + (size_t)(cl + 1) * 512);
                myssq += x0 * x0 + x1 * x1;
                __half h0 = __float2half_rn(x0), h1 = __float2half_rn(x1);
                wv[k >> 1] = ((uint32_t)__half_as_ushort(h1) << 16) | __half_as_ushort(h0);
            }
            uint4* dst = (uint4*)(orow + ch * 32 + half * 16);
            dst[0] = make_uint4(wv[0], wv[1], wv[2], wv[3]);
            dst[1] = make_uint4(wv[4], wv[5], wv[6], wv[7]);
        }
    }
    ssq[tid] = myssq;
    __syncthreads();
    if (tid < 128)
        g_sinv[(b * 32 + t) * 128 + tid] =
            rsqrtf(fmaxf(ssq[tid] + ssq[tid + 128], 1e-24f));
}

// ===========================================================================
// k_gemm: fp16 MMA from L2-resident B image + epilogue + last-CTA final.
#define SM_A    0
#define SM_B    32768     // 4 chunks x 16KB
#define SM_SINV 98304
#define SM_NEG  98816
#define SM_CAPC 99072
#define SM_CAPS 99088
#define SM_CAPP 99344
#define SM_FLAG 99600
#define SM_RED  99616
#define GM_SMEM 100352

__global__ void __launch_bounds__(256, 2) k_gemm(const float* __restrict__ iou,
                                                 float* __restrict__ out) {
    extern __shared__ __align__(128) char sm[];
    uint32_t sb = smem_u32(sm);
    int tid = threadIdx.x;
    int t = blockIdx.x, b = blockIdx.y;
    int ij0 = t * 128, i0 = 2 * t;
    int f0 = i0 >> 3, f1 = (i0 + 1) >> 3;
    int pstart0 = f0 * 8, pstart1 = 64 + f1 * 8;

    float* sinv = (float*)(sm + SM_SINV);
    float* sneg = (float*)(sm + SM_NEG);
    int* capc = (int*)(sm + SM_CAPC);
    int* caps = (int*)(sm + SM_CAPS);
    int* capp = (int*)(sm + SM_CAPP);
    int* flag = (int*)(sm + SM_FLAG);
    float* red = (float*)(sm + SM_RED);

    // prologue: group0 = A + chunk0; groups 1..3 = chunks 1..3
    int pl_p = tid >> 1, pl_u0 = (tid & 1) * 4;
    bool pl_act = (pl_p < 64) ? (pl_p >= pstart0) : (pl_p >= pstart1);
    const char* brow = (const char*)g_Bimg4 +
                       ((size_t)((b * 32 + t) * 128) + pl_p) * 512;
    uint32_t bdst = sb + SM_B + pl_p * 128;
    int psw7 = pl_p & 7;
#pragma unroll
    for (int r = 0; r < 8; r++)
        CP16(sb + SM_A + tid * 16 + r * 4096, (const char*)g_Aimg + tid * 16 + r * 4096);
#pragma unroll
    for (int kc = 0; kc < 4; kc++) {
        if (pl_act) {
#pragma unroll
            for (int i = 0; i < 4; i++) {
                int u = pl_u0 + i;
                CP16(bdst + kc * 16384 + ((u ^ psw7) << 4), brow + kc * 128 + u * 16);
            }
        }
        CP_COMMIT();
    }

    if (tid == 0) *capc = 0;
    if (tid < 64) sneg[tid] = 0.f;
    if (tid < 128) sinv[tid] = g_sinv[(b * 32 + t) * 128 + tid];
    __syncthreads();                 // order capc=0 before capture-list build
    if (tid >= 64 && tid < 128) {
        int s = tid - 64;
        if (g_videoOf[s] == b) {
            int tk = g_topk[s];
            if (tk >= ij0 && tk < ij0 + 128) {
                int c = atomicAdd(capc, 1);
                caps[c] = s;
                capp[c] = tk - ij0;
            }
        }
    }

    int lane = tid & 31, w = tid >> 5;
    int mrow = (w >> 1) * 16;
    int nh = w & 1;
    int fmin = nh ? f1 : f0;
    int pb = nh * 64;

    int g = lane >> 3, r = lane & 7;
    int am = mrow + ((g & 1) << 3) + r;
    uint32_t Abase_m = sb + SM_A + am * 512;
    int am7 = am & 7;
    int akoff = (g >> 1) << 3;
    int pB = pb + ((g & 1) << 3) + r;
    uint32_t Bbase_p = sb + SM_B + pB * 128;
    int pB7 = pB & 7;
    int bkoff = (g >> 1) << 3;

    float acc[32];
#pragma unroll
    for (int i = 0; i < 32; i++) acc[i] = 0.f;

#pragma unroll
    for (int kc = 0; kc < 4; kc++) {
        if (kc == 0) asm volatile("cp.async.wait_group 3;");
        else if (kc == 1) asm volatile("cp.async.wait_group 2;");
        else if (kc == 2) asm volatile("cp.async.wait_group 1;");
        else asm volatile("cp.async.wait_group 0;");
        __syncthreads();
#pragma unroll
        for (int kk = 0; kk < 4; kk++) {
            int kA = kc * 64 + kk * 16 + akoff;
            uint32_t aadr = Abase_m + (((kA >> 3) ^ am7) << 4);
            uint32_t a0, a1, a2, a3;
            LDSM4(a0, a1, a2, a3, aadr);
            int kB = kk * 16 + bkoff;
            uint32_t bsw = (((kB >> 3) ^ pB7) << 4);
#pragma unroll
            for (int fp = 0; fp < 4; fp++) {
                int f = fp * 2;
                if (f + 1 < fmin) continue;
                uint32_t badr = Bbase_p + kc * 16384 + f * 1024 + bsw;
                uint32_t b0, b1, b2, b3;
                LDSM4(b0, b1, b2, b3, badr);
                if (f >= fmin) MMAF16(acc + f * 4, a0, a1, a2, a3, b0, b2);
                MMAF16(acc + f * 4 + 4, a0, a1, a2, a3, b1, b3);
            }
        }
    }
    __syncthreads();

    // epilogue
    int ncap = *capc;
    int s0 = mrow + (lane >> 2), s1 = s0 + 8;
    bool home0 = (g_videoOf[s0] == b), home1 = (g_videoOf[s1] == b);
    const float* iou0 = iou + (size_t)s0 * N2 + ij0;
    const float* iou1 = iou + (size_t)s1 * N2 + ij0;
    float ls0 = 0.f, ls1 = 0.f;
#pragma unroll
    for (int f = 0; f < 8; f++) {
        if (f < fmin) continue;
#pragma unroll
        for (int e = 0; e < 2; e++) {
            int pl = pb + f * 8 + 2 * (lane & 3) + e;
            int ij = ij0 + pl;
            if ((ij & 63) < (ij >> 6)) continue;
            float inv = sinv[pl];
            float sc0 = acc[f * 4 + e] * inv;
            float sc1 = acc[f * 4 + 2 + e] * inv;
            if (!(home0 && iou0[pl] > 0.5f)) ls0 += __expf(sc0 * 10.f);
            if (!(home1 && iou1[pl] > 0.5f)) ls1 += __expf(sc1 * 10.f);
            for (int cc = 0; cc < ncap; cc++)
                if (capp[cc] == pl) {
                    g_all[caps[cc] * SS + s0] = sc0;
                    g_all[caps[cc] * SS + s1] = sc1;
                }
        }
    }
    ls0 += __shfl_xor_sync(0xffffffffu, ls0, 1);
    ls0 += __shfl_xor_sync(0xffffffffu, ls0, 2);
    ls1 += __shfl_xor_sync(0xffffffffu, ls1, 1);
    ls1 += __shfl_xor_sync(0xffffffffu, ls1, 2);
    if ((lane & 3) == 0) {
        atomicAdd(&sneg[s0], ls0);
        atomicAdd(&sneg[s1], ls1);
    }
    __syncthreads();
    if (tid < 64) atomicAdd(&g_negsum[tid], sneg[tid]);

    __threadfence();
    __syncthreads();
    if (tid == 0) *flag = (atomicAdd(&g_done, 1u) == (unsigned)(gridDim.x * gridDim.y - 1));
    __syncthreads();
    if (*flag) {
        if (tid < 64) {
            int s = tid;
            float pos = __ldcg(&g_all[s * SS + s]);
            float sum = 0.f;
            for (int u = 0; u < SS; u++)
                if (u != s) sum += expf(__ldcg(&g_all[s * SS + u]) * 10.f);
            float pv = pos * 10.f;
            red[s] = -(pv - logf(expf(pv) + sum));
            red[64 + s] = -(pv - logf(expf(pv) + __ldcg(&g_negsum[s])));
        }
        __syncthreads();
        if (tid == 0) {
            float a = 0.f, bq = 0.f;
            for (int u = 0; u < SS; u++) { a += red[u]; bq += red[64 + u]; }
            out[0] = a / SS;
            out[1] = bq / SS;
        }
    }
}

// ---------------------------------------------------------------------------
extern "C" void kernel_launch(void* const* d_in, const int* in_sizes, int n_in,
                              void* d_out, int out_size) {
    const float* video = (const float*)d_in[0];
    const float* sents = (const float*)d_in[1];
    const int*   ntgt  = (const int*)d_in[2];
    const float* iou   = (const float*)d_in[3];
    float* out = (float*)d_out;

    cudaFuncSetAttribute(k_convert, cudaFuncAttributeMaxDynamicSharedMemorySize, CV_SMEM);
    cudaFuncSetAttribute(k_convert, cudaFuncAttributePreferredSharedMemoryCarveout, 100);
    cudaFuncSetAttribute(k_gemm, cudaFuncAttributeMaxDynamicSharedMemorySize, GM_SMEM);
    cudaFuncSetAttribute(k_gemm, cudaFuncAttributePreferredSharedMemoryCarveout, 100);

    k_convert<<<1089, 256, CV_SMEM>>>(video, sents, iou, ntgt);
    k_gemm<<<dim3(32, BB), 256, GM_SMEM>>>(iou, out);
}

// round 9
// speedup vs baseline: 1.4175x; 1.4175x over previous
#include <cuda_runtime.h>
#include <cuda_fp16.h>
#include <cstdint>
#include <math.h>

#define BB 32
#define SS 64
#define CC 256
#define N2 4096

__device__ int      g_topk[SS];
__device__ int      g_vstart[BB + 1];
__device__ float    g_negsum[SS];
__device__ float    g_all[SS * SS];
__device__ uint4    g_Afr[16 * 4 * 32];   // A in MMA-fragment order [ks][mt][lane]
__device__ unsigned g_done;

#define MMAF16(d, a0, a1, a2, a3, b0, b1) \
    asm volatile("mma.sync.aligned.m16n8k16.row.col.f32.f16.f16.f32 " \
                 "{%0,%1,%2,%3}, {%4,%5,%6,%7}, {%8,%9}, {%0,%1,%2,%3};" \
                 : "+f"((d)[0]), "+f"((d)[1]), "+f"((d)[2]), "+f"((d)[3]) \
                 : "r"(a0), "r"(a1), "r"(a2), "r"(a3), "r"(b0), "r"(b1))

// ---------------------------------------------------------------------------
// k_prep: bid<64 = sentence s: normalize -> fragment-order A; iou argmax.
//         bid==64: vstart prefix + negsum + g_done init.
__global__ void k_prep(const float* __restrict__ sents, const float* __restrict__ iou,
                       const int* __restrict__ ntgt) {
    int bid = blockIdx.x, tid = threadIdx.x;
    if (bid == 64) {
        if (tid < SS) g_negsum[tid] = 0.f;
        if (tid == 0) {
            g_done = 0u;
            int acc = 0;
            g_vstart[0] = 0;
            for (int b = 0; b < BB; b++) {
                acc += ntgt[b];
                if (acc > SS) acc = SS;
                g_vstart[b + 1] = acc;
            }
        }
        return;
    }
    int s = bid;
    int lane = tid & 31, w = tid >> 5;
    __shared__ float wsum[8];
    __shared__ float amax[8];
    __shared__ int   aidx[8];

    float x = sents[s * CC + tid];
    float q = x * x;
#pragma unroll
    for (int o = 16; o; o >>= 1) q += __shfl_xor_sync(~0u, q, o);
    if (lane == 0) wsum[w] = q;
    __syncthreads();
    float tot = wsum[0] + wsum[1] + wsum[2] + wsum[3] +
                wsum[4] + wsum[5] + wsum[6] + wsum[7];
    float inv = 1.f / fmaxf(sqrtf(tot), 1e-12f);
    __half h = __float2half_rn(x * inv);
    int c = tid;
    // fragment-order byte offset: a0/a1/a2/a3 packed per lane as uint4
    int u4 = ((c >> 4) * 4 + (s >> 4)) * 32 + (s & 7) * 4 + ((c & 7) >> 1);
    int byte = u4 * 16 + ((s >> 3) & 1) * 4 + ((c >> 3) & 1) * 8 + (c & 1) * 2;
    *(__half*)((char*)g_Afr + byte) = h;

    float best = -1.f;
    int bi = 0;
    const float* irow = iou + (size_t)s * N2;
#pragma unroll
    for (int k = 0; k < 16; k++) {
        int ij = tid + 256 * k;
        if ((ij & 63) >= (ij >> 6)) {
            float v = irow[ij];
            if (v > best) { best = v; bi = ij; }
        }
    }
#pragma unroll
    for (int o = 16; o; o >>= 1) {
        float ov = __shfl_xor_sync(~0u, best, o);
        int   oi = __shfl_xor_sync(~0u, bi, o);
        if (ov > best || (ov == best && oi < bi)) { best = ov; bi = oi; }
    }
    if (lane == 0) { amax[w] = best; aidx[w] = bi; }
    __syncthreads();
    if (tid == 0) {
        float bb = amax[0]; int ii = aidx[0];
        for (int k = 1; k < 8; k++)
            if (amax[k] > bb || (amax[k] == bb && aidx[k] < ii)) { bb = amax[k]; ii = aidx[k]; }
        g_topk[s] = ii;
    }
}

// ---------------------------------------------------------------------------
// k_main: warp-autonomous. Each warp = one 16-prop strip x 64 sents x K=256.
// 160 strips/video, grid (20, 32), 8 warps/CTA. No mainloop barriers.
__global__ void __launch_bounds__(256, 3) k_main(const float* __restrict__ video,
                                                 const float* __restrict__ iou,
                                                 float* __restrict__ out) {
    __shared__ float sneg[SS];
    __shared__ float red[128];
    __shared__ int   flag;

    int tid = threadIdx.x;
    int lane = tid & 31, w = tid >> 5;
    int b = blockIdx.y;
    int sid = blockIdx.x * 8 + w;          // 0..159

    // strip -> (row i, 16-col block kq)
    int i, kq;
    if (sid < 64)       { i = sid >> 2;               kq = sid & 3; }
    else if (sid < 112) { int r = sid - 64;  i = 16 + r / 3;  kq = r % 3 + 1; }
    else if (sid < 144) { int r = sid - 112; i = 32 + (r >> 1); kq = (r & 1) + 2; }
    else                { i = 48 + (sid - 144);        kq = 3; }
    int j0 = kq * 16;
    int p0 = i * 64 + j0;

    if (tid < SS) sneg[tid] = 0.f;
    __syncthreads();

    int q = lane & 3, nl = lane >> 2;
    const float* B0 = video + (size_t)b * CC * N2 + p0 + nl;   // prop p0+nl
    const float* B1 = B0 + 8;                                   // prop p0+8+nl
    const uint4* Af = g_Afr + lane;

    float acc[32];
#pragma unroll
    for (int k = 0; k < 32; k++) acc[k] = 0.f;
    float ss0 = 0.f, ss1 = 0.f;

#pragma unroll 4
    for (int ks = 0; ks < 16; ks++) {
        size_t kb = (size_t)(ks * 16 + 2 * q) * N2;
        const float* c0 = B0 + kb;
        const float* c1 = B1 + kb;
        float x0 = c0[0], x1 = c0[N2], x2 = c0[8 * N2], x3 = c0[9 * N2];
        float y0 = c1[0], y1 = c1[N2], y2 = c1[8 * N2], y3 = c1[9 * N2];
        ss0 += x0 * x0 + x1 * x1 + x2 * x2 + x3 * x3;
        ss1 += y0 * y0 + y1 * y1 + y2 * y2 + y3 * y3;
        __half2 p00 = __floats2half2_rn(x0, x1);
        __half2 p01 = __floats2half2_rn(x2, x3);
        __half2 p10 = __floats2half2_rn(y0, y1);
        __half2 p11 = __floats2half2_rn(y2, y3);
        uint32_t b00 = *(uint32_t*)&p00, b01 = *(uint32_t*)&p01;
        uint32_t b10 = *(uint32_t*)&p10, b11 = *(uint32_t*)&p11;
#pragma unroll
        for (int mt = 0; mt < 4; mt++) {
            uint4 a = Af[(ks * 4 + mt) * 32];
            MMAF16(acc + mt * 8,     a.x, a.y, a.z, a.w, b00, b01);
            MMAF16(acc + mt * 8 + 4, a.x, a.y, a.z, a.w, b10, b11);
        }
    }

    // per-prop inverse norms: quad holds prop (nl) channels
    ss0 += __shfl_xor_sync(~0u, ss0, 1); ss0 += __shfl_xor_sync(~0u, ss0, 2);
    ss1 += __shfl_xor_sync(~0u, ss1, 1); ss1 += __shfl_xor_sync(~0u, ss1, 2);
    float inv0 = rsqrtf(fmaxf(ss0, 1e-24f));   // prop p0+nl
    float inv1 = rsqrtf(fmaxf(ss1, 1e-24f));   // prop p0+8+nl
    // redistribute to this lane's accumulator columns
    float invc[4];
    invc[0] = __shfl_sync(~0u, inv0, 8 * q);
    invc[1] = __shfl_sync(~0u, inv0, 8 * q + 4);
    invc[2] = __shfl_sync(~0u, inv1, 8 * q);
    invc[3] = __shfl_sync(~0u, inv1, 8 * q + 4);

    int jc[4];
    jc[0] = j0 + 2 * q;     jc[1] = jc[0] + 1;
    jc[2] = j0 + 8 + 2 * q; jc[3] = jc[2] + 1;
    bool vj[4];
#pragma unroll
    for (int e = 0; e < 4; e++) vj[e] = (jc[e] >= i);

    int vs0 = g_vstart[b], vs1 = g_vstart[b + 1];
    // capture list: home sentences whose topk prop is in this strip
    int nc = 0, capC[4], capS4[4];
    for (int cs = vs0; cs < vs1; cs++) {
        int rel = g_topk[cs] - i * 64 - j0;
        if (rel >= 0 && rel < 16 && nc < 4) { capC[nc] = j0 + rel; capS4[nc] = cs; nc++; }
    }

    float rsum[8];
#pragma unroll
    for (int mt = 0; mt < 4; mt++) {
        int sA = mt * 16 + nl, sB = sA + 8;
        bool hA = (sA >= vs0 && sA < vs1);
        bool hB = (sB >= vs0 && sB < vs1);
        float rA = 0.f, rB = 0.f;
#pragma unroll
        for (int e = 0; e < 4; e++) {
            int blk = e >> 1, par = e & 1;
            float scA = acc[mt * 8 + blk * 4 + par] * invc[e];
            float scB = acc[mt * 8 + blk * 4 + 2 + par] * invc[e];
            if (vj[e]) {
                int ij = i * 64 + jc[e];
                bool posA = hA && (iou[(size_t)sA * N2 + ij] > 0.5f);
                bool posB = hB && (iou[(size_t)sB * N2 + ij] > 0.5f);
                if (!posA) rA += __expf(scA * 10.f);
                if (!posB) rB += __expf(scB * 10.f);
                for (int cc = 0; cc < nc; cc++)
                    if (capC[cc] == jc[e]) {
                        g_all[capS4[cc] * SS + sA] = scA;
                        g_all[capS4[cc] * SS + sB] = scB;
                    }
            }
        }
        rsum[mt * 2] = rA;
        rsum[mt * 2 + 1] = rB;
    }
    // reduce over quad (same rows, different cols), then smem
#pragma unroll
    for (int k = 0; k < 8; k++) {
        rsum[k] += __shfl_xor_sync(~0u, rsum[k], 1);
        rsum[k] += __shfl_xor_sync(~0u, rsum[k], 2);
    }
    if (q == 0) {
#pragma unroll
        for (int mt = 0; mt < 4; mt++) {
            atomicAdd(&sneg[mt * 16 + nl], rsum[mt * 2]);
            atomicAdd(&sneg[mt * 16 + nl + 8], rsum[mt * 2 + 1]);
        }
    }
    __syncthreads();
    if (tid < SS) atomicAdd(&g_negsum[tid], sneg[tid]);

    // last-CTA final reduction
    __threadfence();
    __syncthreads();
    if (tid == 0) flag = (atomicAdd(&g_done, 1u) == (unsigned)(20 * BB - 1));
    __syncthreads();
    if (flag) {
        if (tid < SS) {
            int s = tid;
            float pos = __ldcg(&g_all[s * SS + s]);
            float sum = 0.f;
            for (int u = 0; u < SS; u++)
                if (u != s) sum += expf(__ldcg(&g_all[s * SS + u]) * 10.f);
            float pv = pos * 10.f;
            red[s] = -(pv - logf(expf(pv) + sum));
            red[64 + s] = -(pv - logf(expf(pv) + __ldcg(&g_negsum[s])));
        }
        __syncthreads();
        if (tid == 0) {
            float a = 0.f, bq = 0.f;
            for (int u = 0; u < SS; u++) { a += red[u]; bq += red[64 + u]; }
            out[0] = a / SS;
            out[1] = bq / SS;
        }
    }
}

// ---------------------------------------------------------------------------
extern "C" void kernel_launch(void* const* d_in, const int* in_sizes, int n_in,
                              void* d_out, int out_size) {
    const float* video = (const float*)d_in[0];
    const float* sents = (const float*)d_in[1];
    const int*   ntgt  = (const int*)d_in[2];
    const float* iou   = (const float*)d_in[3];
    float* out = (float*)d_out;

    k_prep<<<65, 256>>>(sents, iou, ntgt);
    k_main<<<dim3(20, BB), 256>>>(video, iou, out);
}